// round 4
// baseline (speedup 1.0000x reference)
#include <cuda_runtime.h>

#define LSEQ    2048
#define BATCH   32
#define NPAIR   (LSEQ/2)
#define TPB2    128
#define NCHUNK2 16              // TPB2 * NCHUNK2 == LSEQ
#define DT_C    0.01f
#define EPS_C   1e-5f
#define QS_C    (1.4426950408889634f * 0.57735026918962576f)  // log2e / sqrt(3)

typedef unsigned long long ull;

// ---------- f32x2 packed helpers (PTX ISA 8.6, sm_100+) ----------
__device__ __forceinline__ ull fma2(ull a, ull b, ull c) {
    ull d; asm("fma.rn.f32x2 %0, %1, %2, %3;" : "=l"(d) : "l"(a), "l"(b), "l"(c)); return d;
}
__device__ __forceinline__ ull mul2(ull a, ull b) {
    ull d; asm("mul.rn.f32x2 %0, %1, %2;" : "=l"(d) : "l"(a), "l"(b)); return d;
}
__device__ __forceinline__ ull add2(ull a, ull b) {
    ull d; asm("add.rn.f32x2 %0, %1, %2;" : "=l"(d) : "l"(a), "l"(b)); return d;
}
__device__ __forceinline__ ull pk2(float lo, float hi) {
    ull r; asm("mov.b64 %0, {%1, %2};" : "=l"(r) : "f"(lo), "f"(hi)); return r;
}
__device__ __forceinline__ void up2(ull v, float& lo, float& hi) {
    asm("mov.b64 {%0, %1}, %2;" : "=f"(lo), "=f"(hi) : "l"(v));
}
__device__ __forceinline__ float ex2f(float x) {
    float y; asm("ex2.approx.ftz.f32 %0, %1;" : "=f"(y) : "f"(x)); return y;
}

// ---------- static scratch ----------
__device__ ulonglong2 g_P[BATCH][NPAIR];   // (k0e,k0o | k1e,k1o)
__device__ ulonglong2 g_Q[BATCH][NPAIR];   // (k2e,k2o | v0e,v0o)
__device__ ulonglong2 g_R[BATCH][NPAIR];   // (v1e,v1o | v2e,v2o)
__device__ float4     g_QY[BATCH][LSEQ];   // (q0,q1,q2,0) * QS
__device__ float4     g_part[2][BATCH][LSEQ];  // (sum, c0, c1, c2) per segment

// ================= kernel 1: QKV projection =================
__global__ void __launch_bounds__(256)
proj_kernel(const float* __restrict__ inp,
            const float* __restrict__ ipw, const float* __restrict__ ipb,
            const float* __restrict__ sig)
{
    int idx = blockIdx.x * 256 + threadIdx.x;
    if (idx >= BATCH * NPAIR) return;
    int b = idx >> 10, i = idx & (NPAIR - 1);
    int j0 = 2 * i, j1 = 2 * i + 1;

    const float inv0 = 1.0f / (__ldg(&sig[0]) + EPS_C);
    const float inv1 = 1.0f / (__ldg(&sig[1]) + EPS_C);

    float W[27], Bv[9];
    #pragma unroll
    for (int k = 0; k < 27; k++) W[k] = __ldg(&ipw[k]);
    #pragma unroll
    for (int k = 0; k < 9; k++)  Bv[k] = __ldg(&ipb[k]);

    const float* xb = inp + ((size_t)b * LSEQ) * 3;
    float xe0 = xb[j0*3+0], xe1 = xb[j0*3+1]*inv0, xe2 = xb[j0*3+2]*inv1;
    float xo0 = xb[j1*3+0], xo1 = xb[j1*3+1]*inv0, xo2 = xb[j1*3+2]*inv1;

    float qe[3], qo[3], ke[3], ko[3], ve[3], vo[3];
    #pragma unroll
    for (int r = 0; r < 3; r++) {
        qe[r] = fmaf(W[3*r+0], xe0, fmaf(W[3*r+1], xe1, fmaf(W[3*r+2], xe2, Bv[r])));
        qo[r] = fmaf(W[3*r+0], xo0, fmaf(W[3*r+1], xo1, fmaf(W[3*r+2], xo2, Bv[r])));
        ke[r] = fmaf(W[9+3*r+0], xe0, fmaf(W[9+3*r+1], xe1, fmaf(W[9+3*r+2], xe2, Bv[3+r])));
        ko[r] = fmaf(W[9+3*r+0], xo0, fmaf(W[9+3*r+1], xo1, fmaf(W[9+3*r+2], xo2, Bv[3+r])));
        ve[r] = fmaf(W[18+3*r+0], xe0, fmaf(W[18+3*r+1], xe1, fmaf(W[18+3*r+2], xe2, Bv[6+r])));
        vo[r] = fmaf(W[18+3*r+0], xo0, fmaf(W[18+3*r+1], xo1, fmaf(W[18+3*r+2], xo2, Bv[6+r])));
    }
    float4* P = (float4*)&g_P[b][i]; *P = make_float4(ke[0], ko[0], ke[1], ko[1]);
    float4* Q = (float4*)&g_Q[b][i]; *Q = make_float4(ke[2], ko[2], ve[0], vo[0]);
    float4* R = (float4*)&g_R[b][i]; *R = make_float4(ve[1], vo[1], ve[2], vo[2]);
    g_QY[b][j0] = make_float4(qe[0]*QS_C, qe[1]*QS_C, qe[2]*QS_C, 0.f);
    g_QY[b][j1] = make_float4(qo[0]*QS_C, qo[1]*QS_C, qo[2]*QS_C, 0.f);
}

// ================= kernel 2: attention partials (K-split 2-way) =================
__global__ void __launch_bounds__(TPB2)
attn_part_kernel()
{
    const int b = blockIdx.x;
    const int c = blockIdx.y;
    const int s = blockIdx.z;               // key segment 0 or 1
    const int t = threadIdx.x;
    const int q = c * TPB2 + t;
    const int np  = (q + 1) >> 1;           // full key pairs in causal range
    const int mid = c * (TPB2 / 2 / 2) * 2; // c*32: uniform split point (<= np for all t)

    const int i0 = (s == 0) ? 0   : mid;
    const int i1 = (s == 0) ? mid : np;

    float4 qv = g_QY[b][q];
    const ull qp0 = pk2(qv.x, qv.x);
    const ull qp1 = pk2(qv.y, qv.y);
    const ull qp2 = pk2(qv.z, qv.z);

    const ulonglong2* __restrict__ pP = g_P[b];
    const ulonglong2* __restrict__ pQ = g_Q[b];
    const ulonglong2* __restrict__ pR = g_R[b];

    ull sum2 = 0ull, a02 = 0ull, a12 = 0ull, a22 = 0ull;

    #pragma unroll 4
    for (int i = i0; i < i1; i++) {
        ulonglong2 Pv = __ldg(&pP[i]);      // uniform addr across warp -> broadcast
        ulonglong2 Qv = __ldg(&pQ[i]);
        ulonglong2 Rv = __ldg(&pR[i]);
        ull sc = fma2(Pv.x, qp0, fma2(Pv.y, qp1, mul2(Qv.x, qp2)));
        float se, so; up2(sc, se, so);
        ull p = pk2(ex2f(se), ex2f(so));
        sum2 = add2(sum2, p);
        a02 = fma2(p, Qv.y, a02);
        a12 = fma2(p, Rv.x, a12);
        a22 = fma2(p, Rv.y, a22);
    }

    float sl, sh, c0l, c0h, c1l, c1h, c2l, c2h;
    up2(sum2, sl, sh); up2(a02, c0l, c0h); up2(a12, c1l, c1h); up2(a22, c2l, c2h);
    float cs = sl + sh, c0 = c0l + c0h, c1 = c1l + c1h, c2 = c2l + c2h;

    if (s == 1 && (q & 1) == 0) {           // leftover single key j == q (even slot of pair np)
        float4 Pv = __ldg((const float4*)&pP[np]);
        float4 Qv = __ldg((const float4*)&pQ[np]);
        float4 Rv = __ldg((const float4*)&pR[np]);
        float sc = fmaf(qv.x, Pv.x, fmaf(qv.y, Pv.z, qv.z * Qv.x));
        float p = ex2f(sc);
        cs += p; c0 = fmaf(p, Qv.z, c0); c1 = fmaf(p, Rv.x, c1); c2 = fmaf(p, Rv.z, c2);
    }

    g_part[s][b][q] = make_float4(cs, c0, c1, c2);
}

// ================= kernel 3: combine + ODE epilogue =================
__global__ void __launch_bounds__(256)
combine_kernel(const float* __restrict__ opw, const float* __restrict__ opb,
               const float* __restrict__ f1w, const float* __restrict__ f1b,
               const float* __restrict__ f2w, const float* __restrict__ f2b,
               const float* __restrict__ g1w, const float* __restrict__ g1b,
               const float* __restrict__ g2w, const float* __restrict__ g2b,
               const float* __restrict__ m1p, const float* __restrict__ m2p,
               const float* __restrict__ sig,
               float* __restrict__ out)
{
    int idx = blockIdx.x * 256 + threadIdx.x;   // 0 .. BATCH*LSEQ-1
    int b = idx >> 11, q = idx & (LSEQ - 1);

    float4 A = g_part[0][b][q];
    float4 Bp = g_part[1][b][q];
    float cs = A.x + Bp.x, c0 = A.y + Bp.y, c1 = A.z + Bp.z, c2 = A.w + Bp.w;

    const float sc0 = __ldg(&sig[0]) + EPS_C;
    const float sc1 = __ldg(&sig[1]) + EPS_C;
    float wo[9];
    #pragma unroll
    for (int i = 0; i < 9; i++) wo[i] = __ldg(&opw[i]);
    const float bo1 = __ldg(&opb[1]), bo2 = __ldg(&opb[2]);
    const float m1 = __ldg(m1p), m2 = __ldg(m2p);
    float F1[3], F2[3], G1[3], G2[3];
    #pragma unroll
    for (int i = 0; i < 3; i++) {
        F1[i] = __ldg(&f1w[i]); F2[i] = __ldg(&f2w[i]);
        G1[i] = __ldg(&g1w[i]); G2[i] = __ldg(&g2w[i]);
    }
    const float F1b = __ldg(f1b), F2b = __ldg(f2b), G1b = __ldg(g1b), G2b = __ldg(g2b);

    float inv = 1.0f / cs;
    float x0 = c0 * inv, x1 = c1 * inv, x2 = c2 * inv;
    float s1 = fmaf(wo[3], x0, fmaf(wo[4], x1, fmaf(wo[5], x2, bo1)));
    float s2 = fmaf(wo[6], x0, fmaf(wo[7], x1, fmaf(wo[8], x2, bo2)));

    float S2_1, S2_2, S3_1, S3_2, S4_1, S4_2;
    {
        float g1v = (G1[0] + fmaf(G1[1], s1, fmaf(G1[2], s2, G1b))) * m1;
        float g2v = (G2[0] + fmaf(G2[1], s1, fmaf(G2[2], s2, G2b))) * m2;
        S2_1 = fmaf(g1v, DT_C, s1); S2_2 = fmaf(g2v, DT_C, s2);
    }
    {
        float g1v = (G1[0] + fmaf(G1[1], S2_1, fmaf(G1[2], S2_2, G1b))) * m1;
        float g2v = (G2[0] + fmaf(G2[1], S2_1, fmaf(G2[2], S2_2, G2b))) * m2;
        S3_1 = fmaf(g1v, DT_C, S2_1); S3_2 = fmaf(g2v, DT_C, S2_2);
    }
    {
        float g1v = (G1[0] + fmaf(G1[1], S3_1, fmaf(G1[2], S3_2, G1b))) * m1;
        float g2v = (G2[0] + fmaf(G2[1], S3_1, fmaf(G2[2], S3_2, G2b))) * m2;
        S4_1 = fmaf(g1v, DT_C, S3_1); S4_2 = fmaf(g2v, DT_C, S3_2);
    }
    float vd1 = (F1[0] + fmaf(F1[1], S4_1, fmaf(F1[2], S4_2, F1b))) * m1;
    float vd2 = (F2[0] + fmaf(F2[1], S4_1, fmaf(F2[2], S4_2, F2b))) * m2;

    float4* o = (float4*)(out + ((size_t)idx << 3));
    o[0] = make_float4(S2_1 * sc0, S2_2 * sc1, S3_1 * sc0, S3_2 * sc1);
    o[1] = make_float4(S4_1 * sc0, S4_2 * sc1,
                       fmaf(vd1, DT_C, S4_1) * sc0, fmaf(vd2, DT_C, S4_2) * sc1);
}

extern "C" void kernel_launch(void* const* d_in, const int* in_sizes, int n_in,
                              void* d_out, int out_size)
{
    const float* inp = (const float*)d_in[1];
    const float* ipw = (const float*)d_in[2];
    const float* ipb = (const float*)d_in[3];
    const float* opw = (const float*)d_in[4];
    const float* opb = (const float*)d_in[5];
    const float* f1w = (const float*)d_in[6];
    const float* f1b = (const float*)d_in[7];
    const float* f2w = (const float*)d_in[8];
    const float* f2b = (const float*)d_in[9];
    const float* g1w = (const float*)d_in[10];
    const float* g1b = (const float*)d_in[11];
    const float* g2w = (const float*)d_in[12];
    const float* g2b = (const float*)d_in[13];
    const float* m1p = (const float*)d_in[14];
    const float* m2p = (const float*)d_in[15];
    const float* sig = (const float*)d_in[16];
    float* out = (float*)d_out;

    proj_kernel<<<(BATCH * NPAIR + 255) / 256, 256>>>(inp, ipw, ipb, sig);

    dim3 grid(BATCH, NCHUNK2, 2);
    attn_part_kernel<<<grid, TPB2>>>();

    combine_kernel<<<(BATCH * LSEQ) / 256, 256>>>(opw, opb, f1w, f1b, f2w, f2b,
                                                  g1w, g1b, g2w, g2b,
                                                  m1p, m2p, sig, out);
}

// round 5
// speedup vs baseline: 3.7609x; 3.7609x over previous
#include <cuda_runtime.h>

#define LSEQ    2048
#define BATCH   32
#define NPAIR   1024
#define TPB     128
#define NCHUNK  16
#define NSEG    4
#define TILE    32            // key pairs per staged tile
#define DT_C    0.01f
#define EPS_C   1e-5f
#define QS_C    (1.4426950408889634f * 0.57735026918962576f)  // log2e/sqrt(3)

typedef unsigned long long ull;

// ---------- f32x2 packed helpers ----------
__device__ __forceinline__ ull fma2(ull a, ull b, ull c) {
    ull d; asm("fma.rn.f32x2 %0, %1, %2, %3;" : "=l"(d) : "l"(a), "l"(b), "l"(c)); return d;
}
__device__ __forceinline__ ull mul2(ull a, ull b) {
    ull d; asm("mul.rn.f32x2 %0, %1, %2;" : "=l"(d) : "l"(a), "l"(b)); return d;
}
__device__ __forceinline__ ull add2(ull a, ull b) {
    ull d; asm("add.rn.f32x2 %0, %1, %2;" : "=l"(d) : "l"(a), "l"(b)); return d;
}
__device__ __forceinline__ ull pk2(float lo, float hi) {
    ull r; asm("mov.b64 %0, {%1, %2};" : "=l"(r) : "f"(lo), "f"(hi)); return r;
}
__device__ __forceinline__ void up2(ull v, float& lo, float& hi) {
    asm("mov.b64 {%0, %1}, %2;" : "=f"(lo), "=f"(hi) : "l"(v));
}
__device__ __forceinline__ float ex2f(float x) {
    float y; asm("ex2.approx.ftz.f32 %0, %1;" : "=f"(y) : "f"(x)); return y;
}
// ---------- cp.async ----------
__device__ __forceinline__ void cpa16(float4* s, const float4* g) {
    unsigned sa = (unsigned)__cvta_generic_to_shared(s);
    asm volatile("cp.async.cg.shared.global [%0], [%1], 16;" :: "r"(sa), "l"(g));
}
__device__ __forceinline__ void cpcommit() { asm volatile("cp.async.commit_group;"); }
template<int N> __device__ __forceinline__ void cpwait() {
    asm volatile("cp.async.wait_group %0;" :: "n"(N));
}

// ---------- static scratch ----------
__device__ float4 g_P[BATCH][NPAIR];        // (k0e,k0o,k1e,k1o)
__device__ float4 g_Q[BATCH][NPAIR];        // (k2e,k2o,v0e,v0o)
__device__ float4 g_R[BATCH][NPAIR];        // (v1e,v1o,v2e,v2o)
__device__ float4 g_QY[BATCH][LSEQ];        // (q0,q1,q2,0)*QS
__device__ float4 g_part[NSEG][BATCH][LSEQ];

// ================= kernel 1: QKV projection =================
__global__ void __launch_bounds__(256)
proj_kernel(const float* __restrict__ inp,
            const float* __restrict__ ipw, const float* __restrict__ ipb,
            const float* __restrict__ sig)
{
    int idx = blockIdx.x * 256 + threadIdx.x;
    if (idx >= BATCH * NPAIR) return;
    int b = idx >> 10, i = idx & (NPAIR - 1);

    const float* xb = inp + ((size_t)b * LSEQ) * 3;
    const float2* xp = (const float2*)(xb + 6 * i);     // 8B-aligned
    float2 u0 = __ldg(&xp[0]);      // xe0, xe1
    float2 u1 = __ldg(&xp[1]);      // xe2, xo0
    float2 u2 = __ldg(&xp[2]);      // xo1, xo2

    const float inv0 = 1.0f / (__ldg(&sig[0]) + EPS_C);
    const float inv1 = 1.0f / (__ldg(&sig[1]) + EPS_C);

    float W[27], Bv[9];
    #pragma unroll
    for (int k = 0; k < 27; k++) W[k] = __ldg(&ipw[k]);
    #pragma unroll
    for (int k = 0; k < 9; k++)  Bv[k] = __ldg(&ipb[k]);

    float xe0 = u0.x, xe1 = u0.y * inv0, xe2 = u1.x * inv1;
    float xo0 = u1.y, xo1 = u2.x * inv0, xo2 = u2.y * inv1;

    float qe[3], qo[3], ke[3], ko[3], ve[3], vo[3];
    #pragma unroll
    for (int r = 0; r < 3; r++) {
        qe[r] = fmaf(W[3*r+0], xe0, fmaf(W[3*r+1], xe1, fmaf(W[3*r+2], xe2, Bv[r])));
        qo[r] = fmaf(W[3*r+0], xo0, fmaf(W[3*r+1], xo1, fmaf(W[3*r+2], xo2, Bv[r])));
        ke[r] = fmaf(W[9+3*r+0], xe0, fmaf(W[9+3*r+1], xe1, fmaf(W[9+3*r+2], xe2, Bv[3+r])));
        ko[r] = fmaf(W[9+3*r+0], xo0, fmaf(W[9+3*r+1], xo1, fmaf(W[9+3*r+2], xo2, Bv[3+r])));
        ve[r] = fmaf(W[18+3*r+0], xe0, fmaf(W[18+3*r+1], xe1, fmaf(W[18+3*r+2], xe2, Bv[6+r])));
        vo[r] = fmaf(W[18+3*r+0], xo0, fmaf(W[18+3*r+1], xo1, fmaf(W[18+3*r+2], xo2, Bv[6+r])));
    }
    g_P[b][i] = make_float4(ke[0], ko[0], ke[1], ko[1]);
    g_Q[b][i] = make_float4(ke[2], ko[2], ve[0], vo[0]);
    g_R[b][i] = make_float4(ve[1], vo[1], ve[2], vo[2]);
    g_QY[b][2*i]   = make_float4(qe[0]*QS_C, qe[1]*QS_C, qe[2]*QS_C, 0.f);
    g_QY[b][2*i+1] = make_float4(qo[0]*QS_C, qo[1]*QS_C, qo[2]*QS_C, 0.f);
}

// ================= kernel 2: attention partials (smem tiles, K-split x4) =================
__global__ void __launch_bounds__(TPB, 8)
attn_part_kernel()
{
    __shared__ float4 buf[2][3 * TILE];    // [P(32) | Q(32) | R(32)] x double buffer

    const int b = blockIdx.x;
    const int s = blockIdx.y;
    const int c = (NCHUNK - 1) - blockIdx.z;    // long chunks launch first
    const int t = threadIdx.x;
    const int q = c * TPB + t;

    const int segl = (c + 1) * (NPAIR / NCHUNK / NSEG);   // (c+1)*16 pairs
    const int s0 = s * segl;
    const int s1 = s0 + segl;
    const int ntiles = (segl + TILE - 1) / TILE;

    auto stage = [&](int T, int slot) {
        int base = s0 + T * TILE;
        if (t < TILE)            cpa16(&buf[slot][t], &g_P[b][base + t]);
        else if (t < 2 * TILE)   cpa16(&buf[slot][t], &g_Q[b][base + t - TILE]);
        else if (t < 3 * TILE)   cpa16(&buf[slot][t], &g_R[b][base + t - 2 * TILE]);
        cpcommit();
    };

    stage(0, 0);
    if (ntiles > 1) stage(1, 1);

    float4 qv = g_QY[b][q];
    const ull qp0 = pk2(qv.x, qv.x);
    const ull qp1 = pk2(qv.y, qv.y);
    const ull qp2 = pk2(qv.z, qv.z);

    const int la = min(q >> 1, s1 - 1);        // key 2*gp   valid iff gp <= la
    const int lb = min((q - 1) >> 1, s1 - 1);  // key 2*gp+1 valid iff gp <= lb

    ull sum2 = 0ull, a02 = 0ull, a12 = 0ull, a22 = 0ull;

    for (int T = 0; T < ntiles; T++) {
        if (T + 1 < ntiles) cpwait<1>(); else cpwait<0>();
        __syncthreads();
        const ulonglong2* sP = (const ulonglong2*)&buf[T & 1][0];
        const ulonglong2* sQ = (const ulonglong2*)&buf[T & 1][TILE];
        const ulonglong2* sR = (const ulonglong2*)&buf[T & 1][2 * TILE];
        const int p0 = s0 + T * TILE;
        #pragma unroll 4
        for (int i = 0; i < TILE; i++) {
            int gp = p0 + i;
            ulonglong2 Pv = sP[i];
            ulonglong2 Qv = sQ[i];
            ulonglong2 Rv = sR[i];
            ull sc = fma2(Pv.x, qp0, fma2(Pv.y, qp1, mul2(Qv.x, qp2)));
            float se, so; up2(sc, se, so);
            float plo = (gp <= la) ? ex2f(se) : 0.0f;
            float phi = (gp <= lb) ? ex2f(so) : 0.0f;
            ull p = pk2(plo, phi);
            sum2 = add2(sum2, p);
            a02 = fma2(p, Qv.y, a02);
            a12 = fma2(p, Rv.x, a12);
            a22 = fma2(p, Rv.y, a22);
        }
        __syncthreads();
        if (T + 2 < ntiles) stage(T + 2, T & 1);
    }

    float sl, sh, c0l, c0h, c1l, c1h, c2l, c2h;
    up2(sum2, sl, sh); up2(a02, c0l, c0h); up2(a12, c1l, c1h); up2(a22, c2l, c2h);
    g_part[s][b][q] = make_float4(sl + sh, c0l + c0h, c1l + c1h, c2l + c2h);
}

// ================= kernel 3: combine + ODE epilogue =================
__global__ void __launch_bounds__(256)
combine_kernel(const float* __restrict__ opw, const float* __restrict__ opb,
               const float* __restrict__ f1w, const float* __restrict__ f1b,
               const float* __restrict__ f2w, const float* __restrict__ f2b,
               const float* __restrict__ g1w, const float* __restrict__ g1b,
               const float* __restrict__ g2w, const float* __restrict__ g2b,
               const float* __restrict__ m1p, const float* __restrict__ m2p,
               const float* __restrict__ sig,
               float* __restrict__ out)
{
    int idx = blockIdx.x * 256 + threadIdx.x;   // 0 .. BATCH*LSEQ-1
    int b = idx >> 11, q = idx & (LSEQ - 1);

    float4 A = g_part[0][b][q];
    float4 Bp = g_part[1][b][q];
    float4 C = g_part[2][b][q];
    float4 D = g_part[3][b][q];
    float cs = (A.x + Bp.x) + (C.x + D.x);
    float c0 = (A.y + Bp.y) + (C.y + D.y);
    float c1 = (A.z + Bp.z) + (C.z + D.z);
    float c2 = (A.w + Bp.w) + (C.w + D.w);

    const float sc0 = __ldg(&sig[0]) + EPS_C;
    const float sc1 = __ldg(&sig[1]) + EPS_C;
    float wo[9];
    #pragma unroll
    for (int i = 0; i < 9; i++) wo[i] = __ldg(&opw[i]);
    const float bo1 = __ldg(&opb[1]), bo2 = __ldg(&opb[2]);
    const float m1 = __ldg(m1p), m2 = __ldg(m2p);
    float F1[3], F2[3], G1[3], G2[3];
    #pragma unroll
    for (int i = 0; i < 3; i++) {
        F1[i] = __ldg(&f1w[i]); F2[i] = __ldg(&f2w[i]);
        G1[i] = __ldg(&g1w[i]); G2[i] = __ldg(&g2w[i]);
    }
    const float F1b = __ldg(f1b), F2b = __ldg(f2b), G1b = __ldg(g1b), G2b = __ldg(g2b);

    float inv = 1.0f / cs;
    float x0 = c0 * inv, x1 = c1 * inv, x2 = c2 * inv;
    float s1 = fmaf(wo[3], x0, fmaf(wo[4], x1, fmaf(wo[5], x2, bo1)));
    float s2 = fmaf(wo[6], x0, fmaf(wo[7], x1, fmaf(wo[8], x2, bo2)));

    float S2_1, S2_2, S3_1, S3_2, S4_1, S4_2;
    {
        float g1v = (G1[0] + fmaf(G1[1], s1, fmaf(G1[2], s2, G1b))) * m1;
        float g2v = (G2[0] + fmaf(G2[1], s1, fmaf(G2[2], s2, G2b))) * m2;
        S2_1 = fmaf(g1v, DT_C, s1); S2_2 = fmaf(g2v, DT_C, s2);
    }
    {
        float g1v = (G1[0] + fmaf(G1[1], S2_1, fmaf(G1[2], S2_2, G1b))) * m1;
        float g2v = (G2[0] + fmaf(G2[1], S2_1, fmaf(G2[2], S2_2, G2b))) * m2;
        S3_1 = fmaf(g1v, DT_C, S2_1); S3_2 = fmaf(g2v, DT_C, S2_2);
    }
    {
        float g1v = (G1[0] + fmaf(G1[1], S3_1, fmaf(G1[2], S3_2, G1b))) * m1;
        float g2v = (G2[0] + fmaf(G2[1], S3_1, fmaf(G2[2], S3_2, G2b))) * m2;
        S4_1 = fmaf(g1v, DT_C, S3_1); S4_2 = fmaf(g2v, DT_C, S3_2);
    }
    float vd1 = (F1[0] + fmaf(F1[1], S4_1, fmaf(F1[2], S4_2, F1b))) * m1;
    float vd2 = (F2[0] + fmaf(F2[1], S4_1, fmaf(F2[2], S4_2, F2b))) * m2;

    float4* o = (float4*)(out + ((size_t)idx << 3));
    o[0] = make_float4(S2_1 * sc0, S2_2 * sc1, S3_1 * sc0, S3_2 * sc1);
    o[1] = make_float4(S4_1 * sc0, S4_2 * sc1,
                       fmaf(vd1, DT_C, S4_1) * sc0, fmaf(vd2, DT_C, S4_2) * sc1);
}

extern "C" void kernel_launch(void* const* d_in, const int* in_sizes, int n_in,
                              void* d_out, int out_size)
{
    const float* inp = (const float*)d_in[1];
    const float* ipw = (const float*)d_in[2];
    const float* ipb = (const float*)d_in[3];
    const float* opw = (const float*)d_in[4];
    const float* opb = (const float*)d_in[5];
    const float* f1w = (const float*)d_in[6];
    const float* f1b = (const float*)d_in[7];
    const float* f2w = (const float*)d_in[8];
    const float* f2b = (const float*)d_in[9];
    const float* g1w = (const float*)d_in[10];
    const float* g1b = (const float*)d_in[11];
    const float* g2w = (const float*)d_in[12];
    const float* g2b = (const float*)d_in[13];
    const float* m1p = (const float*)d_in[14];
    const float* m2p = (const float*)d_in[15];
    const float* sig = (const float*)d_in[16];
    float* out = (float*)d_out;

    proj_kernel<<<(BATCH * NPAIR + 255) / 256, 256>>>(inp, ipw, ipb, sig);

    dim3 grid(BATCH, NSEG, NCHUNK);
    attn_part_kernel<<<grid, TPB>>>();

    combine_kernel<<<(BATCH * LSEQ) / 256, 256>>>(opw, opb, f1w, f1b, f2w, f2b,
                                                  g1w, g1b, g2w, g2b,
                                                  m1p, m2p, sig, out);
}

// round 6
// speedup vs baseline: 4.5890x; 1.2202x over previous
#include <cuda_runtime.h>

#define LSEQ    2048
#define BATCH   32
#define NPAIR   1024
#define TPB     128
#define NCHUNK  16
#define NSEG    4
#define SEGMAX  256           // max pairs per segment (c=15)
#define DT_C    0.01f
#define EPS_C   1e-5f
#define QS_C    (1.4426950408889634f * 0.57735026918962576f)  // log2e/sqrt(3)

typedef unsigned long long ull;

__device__ __forceinline__ ull fma2(ull a, ull b, ull c) {
    ull d; asm("fma.rn.f32x2 %0, %1, %2, %3;" : "=l"(d) : "l"(a), "l"(b), "l"(c)); return d;
}
__device__ __forceinline__ ull mul2(ull a, ull b) {
    ull d; asm("mul.rn.f32x2 %0, %1, %2;" : "=l"(d) : "l"(a), "l"(b)); return d;
}
__device__ __forceinline__ ull add2(ull a, ull b) {
    ull d; asm("add.rn.f32x2 %0, %1, %2;" : "=l"(d) : "l"(a), "l"(b)); return d;
}
__device__ __forceinline__ ull pk2(float lo, float hi) {
    ull r; asm("mov.b64 %0, {%1, %2};" : "=l"(r) : "f"(lo), "f"(hi)); return r;
}
__device__ __forceinline__ void up2(ull v, float& lo, float& hi) {
    asm("mov.b64 {%0, %1}, %2;" : "=f"(lo), "=f"(hi) : "l"(v));
}
__device__ __forceinline__ float ex2f(float x) {
    float y; asm("ex2.approx.ftz.f32 %0, %1;" : "=f"(y) : "f"(x)); return y;
}

__device__ float4 g_part[NSEG][BATCH][LSEQ];   // (sum, c0, c1, c2)

// ======== kernel 1: fused projection + attention partials (K-split x4) ========
__global__ void __launch_bounds__(TPB, 8)
attn_part_kernel(const float* __restrict__ inp,
                 const float* __restrict__ ipw, const float* __restrict__ ipb,
                 const float* __restrict__ sig)
{
    __shared__ float4 sP[SEGMAX];   // (k0e,k0o,k1e,k1o)
    __shared__ float4 sQ[SEGMAX];   // (k2e,k2o,v0e,v0o)
    __shared__ float4 sR[SEGMAX];   // (v1e,v1o,v2e,v2o)

    const int b = blockIdx.x;
    const int s = blockIdx.y;
    const int c = (NCHUNK - 1) - blockIdx.z;        // long chunks first
    const int t = threadIdx.x;
    const int q = c * TPB + t;

    const int segl = (c + 1) * (NPAIR / NCHUNK / NSEG);   // (c+1)*16
    const int s0 = s * segl;

    const float inv0 = 1.0f / (__ldg(&sig[0]) + EPS_C);
    const float inv1 = 1.0f / (__ldg(&sig[1]) + EPS_C);
    const float* xb = inp + ((size_t)b * LSEQ) * 3;

    // ---- project this segment's K/V pairs into smem ----
    {
        float WK[9], WV[9], BK[3], BV[3];
        #pragma unroll
        for (int k = 0; k < 9; k++) { WK[k] = __ldg(&ipw[9 + k]); WV[k] = __ldg(&ipw[18 + k]); }
        #pragma unroll
        for (int k = 0; k < 3; k++) { BK[k] = __ldg(&ipb[3 + k]); BV[k] = __ldg(&ipb[6 + k]); }

        for (int i = t; i < segl; i += TPB) {
            const float2* xp = (const float2*)(xb + 6 * (s0 + i));
            float2 u0 = __ldg(&xp[0]);
            float2 u1 = __ldg(&xp[1]);
            float2 u2 = __ldg(&xp[2]);
            float xe0 = u0.x, xe1 = u0.y * inv0, xe2 = u1.x * inv1;
            float xo0 = u1.y, xo1 = u2.x * inv0, xo2 = u2.y * inv1;
            float ke[3], ko[3], ve[3], vo[3];
            #pragma unroll
            for (int r = 0; r < 3; r++) {
                ke[r] = fmaf(WK[3*r], xe0, fmaf(WK[3*r+1], xe1, fmaf(WK[3*r+2], xe2, BK[r])));
                ko[r] = fmaf(WK[3*r], xo0, fmaf(WK[3*r+1], xo1, fmaf(WK[3*r+2], xo2, BK[r])));
                ve[r] = fmaf(WV[3*r], xe0, fmaf(WV[3*r+1], xe1, fmaf(WV[3*r+2], xe2, BV[r])));
                vo[r] = fmaf(WV[3*r], xo0, fmaf(WV[3*r+1], xo1, fmaf(WV[3*r+2], xo2, BV[r])));
            }
            sP[i] = make_float4(ke[0], ko[0], ke[1], ko[1]);
            sQ[i] = make_float4(ke[2], ko[2], ve[0], vo[0]);
            sR[i] = make_float4(ve[1], vo[1], ve[2], vo[2]);
        }
    }

    // ---- project own query in registers ----
    ull qp0, qp1, qp2;
    {
        const float* xq = xb + q * 3;
        float x0 = __ldg(&xq[0]), x1 = __ldg(&xq[1]) * inv0, x2 = __ldg(&xq[2]) * inv1;
        float q0 = fmaf(__ldg(&ipw[0]), x0, fmaf(__ldg(&ipw[1]), x1, fmaf(__ldg(&ipw[2]), x2, __ldg(&ipb[0])))) * QS_C;
        float q1 = fmaf(__ldg(&ipw[3]), x0, fmaf(__ldg(&ipw[4]), x1, fmaf(__ldg(&ipw[5]), x2, __ldg(&ipb[1])))) * QS_C;
        float q2 = fmaf(__ldg(&ipw[6]), x0, fmaf(__ldg(&ipw[7]), x1, fmaf(__ldg(&ipw[8]), x2, __ldg(&ipb[2])))) * QS_C;
        qp0 = pk2(q0, q0); qp1 = pk2(q1, q1); qp2 = pk2(q2, q2);
    }

    __syncthreads();

    // ---- warp-uniform causal split: unmasked bulk + masked diagonal band ----
    const int qbase = c * TPB + (t & ~31);
    const int lbmin = (qbase - 1) >> 1;                 // arithmetic shift ok
    const int lamax = (qbase + 31) >> 1;
    const int B1 = min(segl, max(0, lbmin + 1 - s0));   // pairs valid for ALL lanes
    const int B2 = min(segl, max(0, lamax + 1 - s0));   // pairs valid for SOME lane
    const int la = q >> 1;                              // even key 2gp valid iff gp<=la
    const int lb = (q - 1) >> 1;                        // odd  key 2gp+1 valid iff gp<=lb

    const ulonglong2* pP = (const ulonglong2*)sP;
    const ulonglong2* pQ = (const ulonglong2*)sQ;
    const ulonglong2* pR = (const ulonglong2*)sR;

    ull sum2 = 0ull, a02 = 0ull, a12 = 0ull, a22 = 0ull;

    #pragma unroll 4
    for (int i = 0; i < B1; i++) {                      // no masking
        ulonglong2 Pv = pP[i];
        ulonglong2 Qv = pQ[i];
        ulonglong2 Rv = pR[i];
        ull sc = fma2(Pv.x, qp0, fma2(Pv.y, qp1, mul2(Qv.x, qp2)));
        float se, so; up2(sc, se, so);
        ull p = pk2(ex2f(se), ex2f(so));
        sum2 = add2(sum2, p);
        a02 = fma2(p, Qv.y, a02);
        a12 = fma2(p, Rv.x, a12);
        a22 = fma2(p, Rv.y, a22);
    }
    for (int i = B1; i < B2; i++) {                     // diagonal band (<=17 iters)
        int gp = s0 + i;
        ulonglong2 Pv = pP[i];
        ulonglong2 Qv = pQ[i];
        ulonglong2 Rv = pR[i];
        ull sc = fma2(Pv.x, qp0, fma2(Pv.y, qp1, mul2(Qv.x, qp2)));
        float se, so; up2(sc, se, so);
        float plo = (gp <= la) ? ex2f(se) : 0.0f;
        float phi = (gp <= lb) ? ex2f(so) : 0.0f;
        ull p = pk2(plo, phi);
        sum2 = add2(sum2, p);
        a02 = fma2(p, Qv.y, a02);
        a12 = fma2(p, Rv.x, a12);
        a22 = fma2(p, Rv.y, a22);
    }

    float sl, sh, c0l, c0h, c1l, c1h, c2l, c2h;
    up2(sum2, sl, sh); up2(a02, c0l, c0h); up2(a12, c1l, c1h); up2(a22, c2l, c2h);
    g_part[s][b][q] = make_float4(sl + sh, c0l + c0h, c1l + c1h, c2l + c2h);
}

// ======== kernel 2: combine + out-proj + ODE epilogue ========
__global__ void __launch_bounds__(256)
combine_kernel(const float* __restrict__ opw, const float* __restrict__ opb,
               const float* __restrict__ f1w, const float* __restrict__ f1b,
               const float* __restrict__ f2w, const float* __restrict__ f2b,
               const float* __restrict__ g1w, const float* __restrict__ g1b,
               const float* __restrict__ g2w, const float* __restrict__ g2b,
               const float* __restrict__ m1p, const float* __restrict__ m2p,
               const float* __restrict__ sig,
               float* __restrict__ out)
{
    int idx = blockIdx.x * 256 + threadIdx.x;   // 0 .. BATCH*LSEQ-1
    int b = idx >> 11, q = idx & (LSEQ - 1);

    float4 A = g_part[0][b][q];
    float4 Bp = g_part[1][b][q];
    float4 C = g_part[2][b][q];
    float4 D = g_part[3][b][q];
    float cs = (A.x + Bp.x) + (C.x + D.x);
    float c0 = (A.y + Bp.y) + (C.y + D.y);
    float c1 = (A.z + Bp.z) + (C.z + D.z);
    float c2 = (A.w + Bp.w) + (C.w + D.w);

    const float sc0 = __ldg(&sig[0]) + EPS_C;
    const float sc1 = __ldg(&sig[1]) + EPS_C;
    float wo[9];
    #pragma unroll
    for (int i = 0; i < 9; i++) wo[i] = __ldg(&opw[i]);
    const float bo1 = __ldg(&opb[1]), bo2 = __ldg(&opb[2]);
    const float m1 = __ldg(m1p), m2 = __ldg(m2p);
    float F1[3], F2[3], G1[3], G2[3];
    #pragma unroll
    for (int i = 0; i < 3; i++) {
        F1[i] = __ldg(&f1w[i]); F2[i] = __ldg(&f2w[i]);
        G1[i] = __ldg(&g1w[i]); G2[i] = __ldg(&g2w[i]);
    }
    const float F1b = __ldg(f1b), F2b = __ldg(f2b), G1b = __ldg(g1b), G2b = __ldg(g2b);

    float inv = 1.0f / cs;
    float x0 = c0 * inv, x1 = c1 * inv, x2 = c2 * inv;
    float s1 = fmaf(wo[3], x0, fmaf(wo[4], x1, fmaf(wo[5], x2, bo1)));
    float s2 = fmaf(wo[6], x0, fmaf(wo[7], x1, fmaf(wo[8], x2, bo2)));

    float S2_1, S2_2, S3_1, S3_2, S4_1, S4_2;
    {
        float g1v = (G1[0] + fmaf(G1[1], s1, fmaf(G1[2], s2, G1b))) * m1;
        float g2v = (G2[0] + fmaf(G2[1], s1, fmaf(G2[2], s2, G2b))) * m2;
        S2_1 = fmaf(g1v, DT_C, s1); S2_2 = fmaf(g2v, DT_C, s2);
    }
    {
        float g1v = (G1[0] + fmaf(G1[1], S2_1, fmaf(G1[2], S2_2, G1b))) * m1;
        float g2v = (G2[0] + fmaf(G2[1], S2_1, fmaf(G2[2], S2_2, G2b))) * m2;
        S3_1 = fmaf(g1v, DT_C, S2_1); S3_2 = fmaf(g2v, DT_C, S2_2);
    }
    {
        float g1v = (G1[0] + fmaf(G1[1], S3_1, fmaf(G1[2], S3_2, G1b))) * m1;
        float g2v = (G2[0] + fmaf(G2[1], S3_1, fmaf(G2[2], S3_2, G2b))) * m2;
        S4_1 = fmaf(g1v, DT_C, S3_1); S4_2 = fmaf(g2v, DT_C, S3_2);
    }
    float vd1 = (F1[0] + fmaf(F1[1], S4_1, fmaf(F1[2], S4_2, F1b))) * m1;
    float vd2 = (F2[0] + fmaf(F2[1], S4_1, fmaf(F2[2], S4_2, F2b))) * m2;

    float4* o = (float4*)(out + ((size_t)idx << 3));
    o[0] = make_float4(S2_1 * sc0, S2_2 * sc1, S3_1 * sc0, S3_2 * sc1);
    o[1] = make_float4(S4_1 * sc0, S4_2 * sc1,
                       fmaf(vd1, DT_C, S4_1) * sc0, fmaf(vd2, DT_C, S4_2) * sc1);
}

extern "C" void kernel_launch(void* const* d_in, const int* in_sizes, int n_in,
                              void* d_out, int out_size)
{
    const float* inp = (const float*)d_in[1];
    const float* ipw = (const float*)d_in[2];
    const float* ipb = (const float*)d_in[3];
    const float* opw = (const float*)d_in[4];
    const float* opb = (const float*)d_in[5];
    const float* f1w = (const float*)d_in[6];
    const float* f1b = (const float*)d_in[7];
    const float* f2w = (const float*)d_in[8];
    const float* f2b = (const float*)d_in[9];
    const float* g1w = (const float*)d_in[10];
    const float* g1b = (const float*)d_in[11];
    const float* g2w = (const float*)d_in[12];
    const float* g2b = (const float*)d_in[13];
    const float* m1p = (const float*)d_in[14];
    const float* m2p = (const float*)d_in[15];
    const float* sig = (const float*)d_in[16];
    float* out = (float*)d_out;

    dim3 grid(BATCH, NSEG, NCHUNK);
    attn_part_kernel<<<grid, TPB>>>(inp, ipw, ipb, sig);

    combine_kernel<<<(BATCH * LSEQ) / 256, 256>>>(opw, opb, f1w, f1b, f2w, f2b,
                                                  g1w, g1b, g2w, g2b,
                                                  m1p, m2p, sig, out);
}